// round 9
// baseline (speedup 1.0000x reference)
#include <cuda_runtime.h>
#include <math.h>

#define HH 36
#define WW 36
#define NPOS (HH*WW)          // 1296
#define KK 31
#define KK2 (KK*KK)

// ---------------- scratch (no allocations allowed) ----------------
__device__ float g_qkv [NPOS*192];
__device__ float g_qkv2[NPOS*192];
__device__ float g_c1  [192*64];
__device__ float g_b1  [192];
__device__ float g_c2  [64*64];
__device__ float g_bf  [64];

// ======================================================================
// setup: blocks 0..242 qkv-GEMM layer1; 243..246 weight folding; 247..330 zero qkv2
// ======================================================================
__global__ __launch_bounds__(256) void setup_kernel(
    const float* __restrict__ x,
    const float* __restrict__ qkv_w1, const float* __restrict__ qkv_b1,
    const float* __restrict__ qkv_w2, const float* __restrict__ proj_w1,
    const float* __restrict__ proj_b1, const float* __restrict__ qkv_b2,
    const float* __restrict__ lin_w, const float* __restrict__ proj_w2,
    const float* __restrict__ proj_b2, const float* __restrict__ dw_b,
    const float* __restrict__ lin_b,
    float* __restrict__ qkv, float* __restrict__ qkv2,
    float* __restrict__ c1, float* __restrict__ b1,
    float* __restrict__ c2, float* __restrict__ bf)
{
    extern __shared__ float sm[];
    const int b = blockIdx.x;
    const int tid = threadIdx.x;

    if (b < 243) {
        float* As = sm;            // [16][68]
        float* Bs = sm + 1088;     // [64][68]
        const int m0 = (b / 3) * 16;
        const int n0 = (b % 3) * 64;
        #pragma unroll
        for (int l = 0; l < 4; l++) {
            int e = tid + l * 256;
            As[(e >> 6) * 68 + (e & 63)] = x[(m0 + (e >> 6)) * 64 + (e & 63)];
        }
        #pragma unroll
        for (int l = 0; l < 16; l++) {
            int e = tid + l * 256;
            Bs[(e >> 6) * 68 + (e & 63)] = qkv_w1[(n0 + (e >> 6)) * 64 + (e & 63)];
        }
        __syncthreads();
        const int col = tid & 63;
        const int tg  = tid >> 6;
        float acc[4] = {0.f, 0.f, 0.f, 0.f};
        #pragma unroll
        for (int kb = 0; kb < 16; kb++) {
            float4 b4 = *(const float4*)&Bs[col * 68 + kb * 4];
            #pragma unroll
            for (int i = 0; i < 4; i++) {
                float4 a4 = *(const float4*)&As[(tg + 4 * i) * 68 + kb * 4];
                acc[i] += a4.x*b4.x + a4.y*b4.y + a4.z*b4.z + a4.w*b4.w;
            }
        }
        float bvv = qkv_b1[n0 + col];
        #pragma unroll
        for (int i = 0; i < 4; i++)
            qkv[(m0 + tg + 4 * i) * 192 + n0 + col] = acc[i] + bvv;
    } else if (b < 247) {
        const int pb = b - 243;
        float* Bs = sm;            // [64][65]
        float* bv = sm + 4160;
        const float* A = (pb < 3) ? (qkv_w2 + pb * 64 * 64) : lin_w;
        const float* B = (pb < 3) ? proj_w1 : proj_w2;
        #pragma unroll
        for (int l = 0; l < 16; l++) {
            int e = tid + l * 256;
            Bs[(e >> 6) * 65 + (e & 63)] = B[e];
        }
        if (tid < 64) bv[tid] = (pb < 3) ? proj_b1[tid] : (proj_b2[tid] + dw_b[tid]);
        __syncthreads();
        const int row = tid >> 2;
        const int qq  = tid & 3;
        // MLP preload of A row (16 independent LDG.128 - no serial chain)
        float4 ar[16];
        const float4* arow4 = (const float4*)(A + row * 64);
        #pragma unroll
        for (int i = 0; i < 16; i++) ar[i] = arow4[i];
        float acc[16] = {};
        float bacc = 0.f;
        #pragma unroll
        for (int kb = 0; kb < 16; kb++) {
            float av[4] = {ar[kb].x, ar[kb].y, ar[kb].z, ar[kb].w};
            #pragma unroll
            for (int c = 0; c < 4; c++) {
                int k = kb * 4 + c;
                float a = av[c];
                bacc += a * bv[k];
                const float* Bp = Bs + k * 65 + qq * 16;
                #pragma unroll
                for (int j = 0; j < 16; j++) acc[j] += a * Bp[j];
            }
        }
        if (pb < 3) {
            #pragma unroll
            for (int j = 0; j < 16; j++)
                c1[(pb * 64 + row) * 64 + qq * 16 + j] = acc[j];
            if (qq == 0) b1[pb * 64 + row] = bacc + qkv_b2[pb * 64 + row];
        } else {
            #pragma unroll
            for (int j = 0; j < 16; j++)
                c2[row * 64 + qq * 16 + j] = acc[j];
            if (qq == 0) bf[row] = bacc + lin_b[row];
        }
    } else {
        float4* d4 = (float4*)qkv2;
        const float4 z = make_float4(0.f, 0.f, 0.f, 0.f);
        for (int i = (b - 247) * 256 + tid; i < NPOS * 192 / 4; i += 84 * 256)
            d4[i] = z;
    }
}

// ======================================================================
// Attention body: 4x2 query tile (4 rows x 2 cols) x 1 head, 256 thr.
// smem floats:
//   s_q    128  @0      (q = qc*4+qr)
//   s_rsum 8    @128
//   s_out  128  @136
//   s_part 1024 @264
//   s_log  8x996 @1288  (stride 996: 16B-aligned AND 4*996 mod 32 = 16 ->
//                        query-column plane groups on different bank quadrants)
//   s_stg  5140 @9256   (8 rows x 32 cols stride 20; zeroed 20-float tail)
// ======================================================================
#define P_LOG 996
#define OFF_RSUM 128
#define OFF_OUT  136
#define OFF_PART 264
#define OFF_LOG  1288
#define OFF_STG  9256
#define SMEM_FLOATS 14396
#define SMEM_BYTES  (SMEM_FLOATS * 4)

#define LOADX(base_, koff) { _Pragma("unroll") for (int l = 0; l < 4; l++) { \
    int idx4 = tid + l * 256; \
    int row = idx4 >> 7, rem = idx4 & 127; \
    int colx = rem >> 2, cg = rem & 3; \
    int gr = min((base_) + row, nrows - 1); \
    int gc = min(c0lo + colx, 35); \
    pre[l] = *(const float4*)(qkv + ((r0lo + gr) * WW + gc) * 192 + (koff) + h * 16 + cg * 4); } }

#define STOREX() { _Pragma("unroll") for (int l = 0; l < 4; l++) { \
    int idx4 = tid + l * 256; \
    int row = idx4 >> 7, rem = idx4 & 127; \
    int colx = rem >> 2, cg = rem & 3; \
    *(float4*)(s_stg + (row * 32 + colx) * 20 + cg * 4) = pre[l]; } }

template<int NOUT>
__device__ __forceinline__ void attn_body(
    const float* __restrict__ qkv, const float* __restrict__ rpb,
    const float* __restrict__ combo, const float* __restrict__ biasv,
    float* __restrict__ dst, int blk)
{
    extern __shared__ float sm[];
    float* s_q    = sm;
    float* s_rsum = sm + OFF_RSUM;
    float* s_out  = sm + OFF_OUT;
    float* s_part = sm + OFF_PART;
    float* s_log  = sm + OFF_LOG;
    float* s_stg  = sm + OFF_STG;

    const int tid  = threadIdx.x;
    const int lane = tid & 31;
    const int w    = tid >> 5;
    const int h    = blk / 162;
    const int t    = blk % 162;
    const int qi0  = (t / 18) * 4;
    const int qj0  = (t % 18) * 2;

    int r0r[4], c0c[2];
    #pragma unroll
    for (int qr = 0; qr < 4; qr++) r0r[qr] = min(max(qi0 + qr - 15, 0), HH - KK);
    #pragma unroll
    for (int qc = 0; qc < 2; qc++) c0c[qc] = min(max(qj0 + qc - 15, 0), WW - KK);
    const int c0lo  = c0c[0];
    const int r0lo  = r0r[0];
    const int nrows = r0r[3] + KK - r0lo;     // 31..34

    if (tid < 128) {
        int q = tid >> 4, ch = tid & 15;
        int pos = (qi0 + (q & 3)) * WW + qj0 + (q >> 2);
        s_q[tid] = qkv[pos * 192 + h * 16 + ch];
    }
    if (tid < 248) {            // pad col 31 of each plane row
        int pl = tid / 31, rw = tid - pl * 31;
        s_log[pl * P_LOG + rw * 32 + 31] = 0.f;
    }
    if (tid < 20) s_stg[5120 + tid] = 0.f;
    __syncthreads();

    // ---------------- pass 1: p = exp(q.K*scale + bias), 4 queries/warp ----------------
    const int qc1 = w & 1;
    const int rp  = w >> 1;       // row parity 0..3: rows rp, rp+4 per chunk
    float4 qreg[4][4];
    #pragma unroll
    for (int qr = 0; qr < 4; qr++) {
        const float4* pq = (const float4*)(s_q + (qc1 * 4 + qr) * 16);
        #pragma unroll
        for (int i = 0; i < 4; i++) qreg[qr][i] = pq[i];
    }
    const int ccb1 = c0c[qc1] - c0lo;
    const int crb1 = c0c[qc1] - (qj0 + qc1) + 30;
    const float* rpb_h = rpb + h * 3721;

    float4 pre[4];
    LOADX(0, 64);
    for (int chunk = 0; chunk < 5; chunk++) {
        const int base = chunk * 8;
        if (base >= nrows) break;
        __syncthreads();
        STOREX();
        __syncthreads();
        if (base + 8 < nrows) LOADX(base + 8, 64);
        #pragma unroll
        for (int rl = 0; rl < 2; rl++) {
            int ric = rp + 4 * rl;
            int rr  = base + ric;
            if (rr >= nrows) break;
            int R = r0lo + rr;
            if (lane <= 30) {
                const float4* kp = (const float4*)(s_stg + (ric * 32 + ccb1 + lane) * 20);
                float4 k0 = kp[0], k1 = kp[1], k2 = kp[2], k3 = kp[3];
                int crel = crb1 + lane;
                #pragma unroll
                for (int qr = 0; qr < 4; qr++) {
                    int kr = R - r0r[qr];
                    if ((unsigned)kr <= 30u) {
                        float a = qreg[qr][0].x*k0.x + qreg[qr][0].y*k0.y + qreg[qr][0].z*k0.z + qreg[qr][0].w*k0.w
                                + qreg[qr][1].x*k1.x + qreg[qr][1].y*k1.y + qreg[qr][1].z*k1.z + qreg[qr][1].w*k1.w
                                + qreg[qr][2].x*k2.x + qreg[qr][2].y*k2.y + qreg[qr][2].z*k2.z + qreg[qr][2].w*k2.w
                                + qreg[qr][3].x*k3.x + qreg[qr][3].y*k3.y + qreg[qr][3].z*k3.z + qreg[qr][3].w*k3.w;
                        s_log[(qc1 * 4 + qr) * P_LOG + kr * 32 + lane] =
                            __expf(a * 0.25f + __ldg(&rpb_h[(R - qi0 - qr + 30) * 61 + crel]));
                    }
                }
            }
        }
    }

    LOADX(0, 128);              // prefetch V chunk 0 under softmax-sum
    __syncthreads();            // pass-1 writes visible

    // ---------------- pass 2: row sums (warp w <-> plane w) ----------------
    {
        float* p = s_log + w * P_LOG;
        float s = 0.f;
        for (int n = lane; n < 992; n += 32) s += p[n];
        #pragma unroll
        for (int off = 16; off; off >>= 1)
            s += __shfl_xor_sync(0xffffffffu, s, off);
        if (lane == 0) s_rsum[w] = 1.0f / s;
    }

    // ---------------- pass 3: out = P.V; warp <-> row; lane = (ks,qc,g) ----------------
    const int ks  = lane >> 2;
    const int qcv = (lane >> 1) & 1;
    const int gv  = lane & 1;
    const int ccb3 = c0c[qcv] - c0lo;
    float4 accA[4], accB[4];
    #pragma unroll
    for (int qr = 0; qr < 4; qr++) {
        accA[qr] = make_float4(0.f,0.f,0.f,0.f);
        accB[qr] = make_float4(0.f,0.f,0.f,0.f);
    }

    for (int chunk = 0; chunk < 5; chunk++) {
        const int base = chunk * 8;
        if (base >= nrows) break;
        if (chunk) __syncthreads();
        STOREX();
        __syncthreads();
        if (base + 8 < nrows) LOADX(base + 8, 128);
        int rr = base + w;
        if (rr < nrows) {
            int R = r0lo + rr;
            const float* vb = s_stg + (w * 32 + ccb3 + ks * 4) * 20 + gv * 8;
            float4 v0a = *(const float4*)(vb);
            float4 v0b = *(const float4*)(vb + 4);
            float4 v1a = *(const float4*)(vb + 20);
            float4 v1b = *(const float4*)(vb + 24);
            float4 v2a = *(const float4*)(vb + 40);
            float4 v2b = *(const float4*)(vb + 44);
            float4 v3a = *(const float4*)(vb + 60);
            float4 v3b = *(const float4*)(vb + 64);
            #pragma unroll
            for (int qr = 0; qr < 4; qr++) {
                int kr = R - r0r[qr];
                if ((unsigned)kr <= 30u) {
                    float4 l4 = *(const float4*)(s_log + (qcv * 4 + qr) * P_LOG + kr * 32 + ks * 4);
                    accA[qr].x += l4.x*v0a.x + l4.y*v1a.x + l4.z*v2a.x + l4.w*v3a.x;
                    accA[qr].y += l4.x*v0a.y + l4.y*v1a.y + l4.z*v2a.y + l4.w*v3a.y;
                    accA[qr].z += l4.x*v0a.z + l4.y*v1a.z + l4.z*v2a.z + l4.w*v3a.z;
                    accA[qr].w += l4.x*v0a.w + l4.y*v1a.w + l4.z*v2a.w + l4.w*v3a.w;
                    accB[qr].x += l4.x*v0b.x + l4.y*v1b.x + l4.z*v2b.x + l4.w*v3b.x;
                    accB[qr].y += l4.x*v0b.y + l4.y*v1b.y + l4.z*v2b.y + l4.w*v3b.y;
                    accB[qr].z += l4.x*v0b.z + l4.y*v1b.z + l4.z*v2b.z + l4.w*v3b.z;
                    accB[qr].w += l4.x*v0b.w + l4.y*v1b.w + l4.z*v2b.w + l4.w*v3b.w;
                }
            }
        }
    }
    // reduce over ks (lane bits 2..4)
    #pragma unroll
    for (int off = 4; off <= 16; off <<= 1) {
        #pragma unroll
        for (int qr = 0; qr < 4; qr++) {
            accA[qr].x += __shfl_xor_sync(0xffffffffu, accA[qr].x, off);
            accA[qr].y += __shfl_xor_sync(0xffffffffu, accA[qr].y, off);
            accA[qr].z += __shfl_xor_sync(0xffffffffu, accA[qr].z, off);
            accA[qr].w += __shfl_xor_sync(0xffffffffu, accA[qr].w, off);
            accB[qr].x += __shfl_xor_sync(0xffffffffu, accB[qr].x, off);
            accB[qr].y += __shfl_xor_sync(0xffffffffu, accB[qr].y, off);
            accB[qr].z += __shfl_xor_sync(0xffffffffu, accB[qr].z, off);
            accB[qr].w += __shfl_xor_sync(0xffffffffu, accB[qr].w, off);
        }
    }
    if (lane < 4) {                       // lane = qc*2+g
        int slot = w * 4 + lane;
        #pragma unroll
        for (int qr = 0; qr < 4; qr++) {
            *(float4*)(s_part + slot * 32 + qr * 8)     = accA[qr];
            *(float4*)(s_part + slot * 32 + qr * 8 + 4) = accB[qr];
        }
    }
    __syncthreads();

    // combine partials over the 8 row-warps; scale; stage combo slice
    if (tid < 128) {
        int q = tid >> 4, ch = tid & 15;      // q = qc*4+qr
        int qc = q >> 2, qr = q & 3;
        int g  = ch >> 3, c8 = ch & 7;
        int off = (qc * 2 + g) * 32 + qr * 8 + c8;
        float s = 0.f;
        #pragma unroll
        for (int ww = 0; ww < 8; ww++) s += s_part[ww * 128 + off];
        s_out[q * 16 + ch] = s * s_rsum[q];
    }
    for (int e = tid; e < NOUT * 4; e += 256) {
        int o = e >> 2, cg = e & 3;
        float4 v = *(const float4*)(combo + o * 64 + h * 16 + cg * 4);
        float* d = s_stg + o * 17 + cg * 4;
        d[0] = v.x; d[1] = v.y; d[2] = v.z; d[3] = v.w;
    }
    __syncthreads();

    // epilogue: dst[pos,:] += out_slice @ combo_colslice
    {
        const int posg = (qi0 + (w & 3)) * WW + qj0 + (w >> 2);
        float sv[16];
        #pragma unroll
        for (int i = 0; i < 16; i++) sv[i] = s_out[w * 16 + i];
        #pragma unroll
        for (int tt = 0; tt < NOUT / 32; tt++) {
            int o = lane + 32 * tt;
            const float* cp = s_stg + o * 17;
            float a = 0.f;
            #pragma unroll
            for (int i = 0; i < 16; i++) a += sv[i] * cp[i];
            if (NOUT == 192 && h == 0) a += biasv[o];
            atomicAdd(dst + posg * NOUT + o, a);
        }
    }
}

// ---------------- conv init path: out = conv(x)@lin^T + bf ----------------
__device__ __forceinline__ void conv_body(
    const float* __restrict__ x, const float* __restrict__ linw,
    const float* __restrict__ dww, const float* __restrict__ bfv,
    float* __restrict__ out, int cb)
{
    extern __shared__ float sm[];
    float* B2  = sm;          // [64][68]
    float* As2 = sm + 4352;   // [16][68]
    float* sdw = sm + 5440;   // 576
    const int tid = threadIdx.x;
    const int m0 = cb * 16;

    #pragma unroll
    for (int l = 0; l < 16; l++) {
        int e = tid + l * 256;
        B2[(e >> 6) * 68 + (e & 63)] = linw[e];
    }
    #pragma unroll
    for (int l = 0; l < 3; l++) {
        int e = tid + l * 256;
        if (e < 576) sdw[e] = dww[e];
    }
    __syncthreads();
    #pragma unroll
    for (int l = 0; l < 4; l++) {
        int e = tid + l * 256;
        int r = e >> 6, c = e & 63;
        int p = m0 + r;
        int i = p / WW, j = p % WW;
        float a = 0.f;
        #pragma unroll
        for (int dy = 0; dy < 3; dy++) {
            int ii = i + dy - 1;
            if (ii < 0 || ii >= HH) continue;
            #pragma unroll
            for (int dx = 0; dx < 3; dx++) {
                int jj = j + dx - 1;
                if (jj < 0 || jj >= WW) continue;
                a += x[(ii * WW + jj) * 64 + c] * sdw[c * 9 + dy * 3 + dx];
            }
        }
        As2[r * 68 + c] = a;
    }
    __syncthreads();
    const int col = tid & 63;
    const int tg  = tid >> 6;
    float acc[4] = {0.f, 0.f, 0.f, 0.f};
    #pragma unroll
    for (int kb = 0; kb < 16; kb++) {
        float4 b2 = *(const float4*)&B2[col * 68 + kb * 4];
        #pragma unroll
        for (int i = 0; i < 4; i++) {
            float4 a2 = *(const float4*)&As2[(tg + 4 * i) * 68 + kb * 4];
            acc[i] += a2.x*b2.x + a2.y*b2.y + a2.z*b2.z + a2.w*b2.w;
        }
    }
    float bvv = bfv[col];
    #pragma unroll
    for (int i = 0; i < 4; i++)
        out[(m0 + tg + 4 * i) * 64 + col] = acc[i] + bvv;
}

__global__ __launch_bounds__(256) void layer1_kernel(
    const float* __restrict__ qkv, const float* __restrict__ rpb,
    const float* __restrict__ c1, const float* __restrict__ b1,
    float* __restrict__ qkv2,
    const float* __restrict__ x, const float* __restrict__ linw,
    const float* __restrict__ dww, const float* __restrict__ bfv,
    float* __restrict__ out)
{
    if (blockIdx.x < 648)
        attn_body<192>(qkv, rpb, c1, b1, qkv2, blockIdx.x);
    else
        conv_body(x, linw, dww, bfv, out, blockIdx.x - 648);
}

__global__ __launch_bounds__(256) void layer2_kernel(
    const float* __restrict__ qkv, const float* __restrict__ rpb,
    const float* __restrict__ c2, float* __restrict__ out)
{
    attn_body<64>(qkv, rpb, c2, (const float*)0, out, blockIdx.x);
}

// ---------------- launcher ----------------
extern "C" void kernel_launch(void* const* d_in, const int* in_sizes, int n_in,
                              void* d_out, int out_size)
{
    const float* x      = (const float*)d_in[0];
    const float* qkv_w1 = (const float*)d_in[3];
    const float* qkv_b1 = (const float*)d_in[4];
    const float* rpb1   = (const float*)d_in[5];
    const float* proj_w1= (const float*)d_in[6];
    const float* proj_b1= (const float*)d_in[7];
    const float* qkv_w2 = (const float*)d_in[8];
    const float* qkv_b2 = (const float*)d_in[9];
    const float* rpb2   = (const float*)d_in[10];
    const float* proj_w2= (const float*)d_in[11];
    const float* proj_b2= (const float*)d_in[12];
    const float* dw_w   = (const float*)d_in[13];
    const float* dw_b   = (const float*)d_in[14];
    const float* lin_w  = (const float*)d_in[15];
    const float* lin_b  = (const float*)d_in[16];
    float* out = (float*)d_out;

    float *p_qkv, *p_qkv2, *p_c1, *p_b1, *p_c2, *p_bf;
    cudaGetSymbolAddress((void**)&p_qkv,  g_qkv);
    cudaGetSymbolAddress((void**)&p_qkv2, g_qkv2);
    cudaGetSymbolAddress((void**)&p_c1,   g_c1);
    cudaGetSymbolAddress((void**)&p_b1,   g_b1);
    cudaGetSymbolAddress((void**)&p_c2,   g_c2);
    cudaGetSymbolAddress((void**)&p_bf,   g_bf);

    cudaFuncSetAttribute(layer1_kernel,
                         cudaFuncAttributeMaxDynamicSharedMemorySize, SMEM_BYTES);
    cudaFuncSetAttribute(layer2_kernel,
                         cudaFuncAttributeMaxDynamicSharedMemorySize, SMEM_BYTES);

    setup_kernel<<<331, 256, 5440 * 4>>>(
        x, qkv_w1, qkv_b1, qkv_w2, proj_w1, proj_b1, qkv_b2,
        lin_w, proj_w2, proj_b2, dw_b, lin_b,
        p_qkv, p_qkv2, p_c1, p_b1, p_c2, p_bf);
    layer1_kernel<<<729, 256, SMEM_BYTES>>>(
        p_qkv, rpb1, p_c1, p_b1, p_qkv2, x, lin_w, dw_w, p_bf, out);
    layer2_kernel<<<648, 256, SMEM_BYTES>>>(p_qkv2, rpb2, p_c2, out);
}

// round 11
// speedup vs baseline: 1.2690x; 1.2690x over previous
#include <cuda_runtime.h>
#include <math.h>

#define HH 36
#define WW 36
#define NPOS (HH*WW)          // 1296
#define KK 31
#define KK2 (KK*KK)

// ---------------- scratch (no allocations allowed) ----------------
__device__ float g_qkv [NPOS*192];
__device__ float g_qkv2[NPOS*192];
__device__ float g_c1  [192*64];
__device__ float g_b1  [192];
__device__ float g_c2  [64*64];
__device__ float g_bf  [64];

// ======================================================================
// setup: blocks 0..242 qkv-GEMM layer1; 243..258 weight folding (16 blocks);
//        259..342 zero qkv2
// ======================================================================
__global__ __launch_bounds__(256) void setup_kernel(
    const float* __restrict__ x,
    const float* __restrict__ qkv_w1, const float* __restrict__ qkv_b1,
    const float* __restrict__ qkv_w2, const float* __restrict__ proj_w1,
    const float* __restrict__ proj_b1, const float* __restrict__ qkv_b2,
    const float* __restrict__ lin_w, const float* __restrict__ proj_w2,
    const float* __restrict__ proj_b2, const float* __restrict__ dw_b,
    const float* __restrict__ lin_b,
    float* __restrict__ qkv, float* __restrict__ qkv2,
    float* __restrict__ c1, float* __restrict__ b1,
    float* __restrict__ c2, float* __restrict__ bf)
{
    extern __shared__ float sm[];
    const int b = blockIdx.x;
    const int tid = threadIdx.x;

    if (b < 243) {
        float* As = sm;            // [16][68]
        float* Bs = sm + 1088;     // [64][68]
        const int m0 = (b / 3) * 16;
        const int n0 = (b % 3) * 64;
        #pragma unroll
        for (int l = 0; l < 4; l++) {
            int e = tid + l * 256;
            As[(e >> 6) * 68 + (e & 63)] = x[(m0 + (e >> 6)) * 64 + (e & 63)];
        }
        #pragma unroll
        for (int l = 0; l < 16; l++) {
            int e = tid + l * 256;
            Bs[(e >> 6) * 68 + (e & 63)] = qkv_w1[(n0 + (e >> 6)) * 64 + (e & 63)];
        }
        __syncthreads();
        const int col = tid & 63;
        const int tg  = tid >> 6;
        float acc[4] = {0.f, 0.f, 0.f, 0.f};
        #pragma unroll
        for (int kb = 0; kb < 16; kb++) {
            float4 b4 = *(const float4*)&Bs[col * 68 + kb * 4];
            #pragma unroll
            for (int i = 0; i < 4; i++) {
                float4 a4 = *(const float4*)&As[(tg + 4 * i) * 68 + kb * 4];
                acc[i] += a4.x*b4.x + a4.y*b4.y + a4.z*b4.z + a4.w*b4.w;
            }
        }
        float bvv = qkv_b1[n0 + col];
        #pragma unroll
        for (int i = 0; i < 4; i++)
            qkv[(m0 + tg + 4 * i) * 192 + n0 + col] = acc[i] + bvv;
    } else if (b < 259) {
        // weight fold: 16 blocks x 16 output rows.
        // fb 0..11 -> c1 rows fb*16.. ; fb 12..15 -> c2 rows (fb-12)*16..
        const int fb = b - 243;
        const bool isC1 = (fb < 12);
        float* Bs = sm;            // [64][68]  (stride 68: 16B-aligned rows)
        float* bv = sm + 4352;     // [64]
        const float* B = isC1 ? proj_w1 : proj_w2;
        #pragma unroll
        for (int l = 0; l < 16; l++) {
            int e = tid + l * 256;
            Bs[(e >> 6) * 68 + (e & 63)] = B[e];
        }
        if (tid < 64) bv[tid] = isC1 ? proj_b1[tid] : (proj_b2[tid] + dw_b[tid]);
        __syncthreads();
        const int lr   = tid >> 4;          // 0..15 local row
        const int qq   = tid & 15;          // output group (4 outputs)
        const int grow = (isC1 ? fb * 16 : (fb - 12) * 16) + lr;
        const float* A = (isC1 ? qkv_w2 : lin_w) + grow * 64;
        float4 ar[16];
        const float4* arow4 = (const float4*)A;
        #pragma unroll
        for (int i = 0; i < 16; i++) ar[i] = arow4[i];
        float acc[4] = {0.f, 0.f, 0.f, 0.f};
        float bacc = 0.f;
        #pragma unroll
        for (int kb = 0; kb < 16; kb++) {
            float av[4] = {ar[kb].x, ar[kb].y, ar[kb].z, ar[kb].w};
            #pragma unroll
            for (int c = 0; c < 4; c++) {
                int k = kb * 4 + c;
                float a = av[c];
                if (qq == 0) bacc += a * bv[k];
                float4 b4 = *(const float4*)&Bs[k * 68 + qq * 4];
                acc[0] += a * b4.x; acc[1] += a * b4.y;
                acc[2] += a * b4.z; acc[3] += a * b4.w;
            }
        }
        float* dstm = isC1 ? c1 : c2;
        #pragma unroll
        for (int j = 0; j < 4; j++)
            dstm[grow * 64 + qq * 4 + j] = acc[j];
        if (qq == 0) {
            if (isC1) b1[grow] = bacc + qkv_b2[grow];
            else      bf[grow] = bacc + lin_b[grow];
        }
    } else {
        float4* d4 = (float4*)qkv2;
        const float4 z = make_float4(0.f, 0.f, 0.f, 0.f);
        for (int i = (b - 259) * 256 + tid; i < NPOS * 192 / 4; i += 84 * 256)
            d4[i] = z;
    }
}

// ======================================================================
// Attention body: 4x2 query tile (4 rows x 2 cols) x 1 head, 256 thr.
// (proven 86.5us layout)
// smem floats:
//   s_q    128  @0      (q = qc*4+qr)
//   s_rsum 8    @128
//   s_out  128  @136
//   s_part 512  @264
//   s_log  8x992 @776
//   s_stg  5140 @8712   (8 rows x 32 cols stride 20; zeroed 20-float tail)
// ======================================================================
#define OFF_RSUM 128
#define OFF_OUT  136
#define OFF_PART 264
#define OFF_LOG  776
#define OFF_STG  8712
#define SMEM_FLOATS 13852
#define SMEM_BYTES  (SMEM_FLOATS * 4)

#define LOADX(base_, koff) { _Pragma("unroll") for (int l = 0; l < 4; l++) { \
    int idx4 = tid + l * 256; \
    int row = idx4 >> 7, rem = idx4 & 127; \
    int colx = rem >> 2, cg = rem & 3; \
    int gr = min((base_) + row, nrows - 1); \
    int gc = min(c0lo + colx, 35); \
    pre[l] = *(const float4*)(qkv + ((r0lo + gr) * WW + gc) * 192 + (koff) + h * 16 + cg * 4); } }

#define STOREX() { _Pragma("unroll") for (int l = 0; l < 4; l++) { \
    int idx4 = tid + l * 256; \
    int row = idx4 >> 7, rem = idx4 & 127; \
    int colx = rem >> 2, cg = rem & 3; \
    *(float4*)(s_stg + (row * 32 + colx) * 20 + cg * 4) = pre[l]; } }

template<int NOUT>
__device__ __forceinline__ void attn_body(
    const float* __restrict__ qkv, const float* __restrict__ rpb,
    const float* __restrict__ combo, const float* __restrict__ biasv,
    float* __restrict__ dst, int blk)
{
    extern __shared__ float sm[];
    float* s_q    = sm;
    float* s_rsum = sm + OFF_RSUM;
    float* s_out  = sm + OFF_OUT;
    float* s_part = sm + OFF_PART;
    float* s_log  = sm + OFF_LOG;
    float* s_stg  = sm + OFF_STG;

    const int tid  = threadIdx.x;
    const int lane = tid & 31;
    const int w    = tid >> 5;
    const int h    = blk / 162;
    const int t    = blk % 162;
    const int qi0  = (t / 18) * 4;
    const int qj0  = (t % 18) * 2;

    int r0r[4], c0c[2];
    #pragma unroll
    for (int qr = 0; qr < 4; qr++) r0r[qr] = min(max(qi0 + qr - 15, 0), HH - KK);
    #pragma unroll
    for (int qc = 0; qc < 2; qc++) c0c[qc] = min(max(qj0 + qc - 15, 0), WW - KK);
    const int c0lo  = c0c[0];
    const int r0lo  = r0r[0];
    const int nrows = r0r[3] + KK - r0lo;     // 31..34

    if (tid < 128) {
        int q = tid >> 4, ch = tid & 15;
        int pos = (qi0 + (q & 3)) * WW + qj0 + (q >> 2);
        s_q[tid] = qkv[pos * 192 + h * 16 + ch];
    }
    if (tid < 248) {            // pad col 31 of each plane row
        int pl = tid / 31, rw = tid - pl * 31;
        s_log[pl * 992 + rw * 32 + 31] = 0.f;
    }
    if (tid < 20) s_stg[5120 + tid] = 0.f;
    __syncthreads();

    // ---------------- pass 1: p = exp(q.K*scale + bias) ----------------
    const int qc1 = w & 1;
    const int qrp = (w >> 1) & 1;     // queries 2*qrp, 2*qrp+1
    const int rh  = w >> 2;           // row parity
    const int qrA = 2 * qrp, qrB = 2 * qrp + 1;
    float4 qa[4], qb[4];
    {
        const float4* pa = (const float4*)(s_q + (qc1 * 4 + qrA) * 16);
        const float4* pb = (const float4*)(s_q + (qc1 * 4 + qrB) * 16);
        #pragma unroll
        for (int i = 0; i < 4; i++) { qa[i] = pa[i]; qb[i] = pb[i]; }
    }
    const int ccb1 = c0c[qc1] - c0lo;
    const int crb1 = c0c[qc1] - (qj0 + qc1) + 30;
    const int r0A = r0r[qrA], r0B = r0r[qrB];
    const int plA = (qc1 * 4 + qrA) * 992;
    const int plB = (qc1 * 4 + qrB) * 992;
    const float* rpb_h = rpb + h * 3721;

    float4 pre[4];
    LOADX(0, 64);
    for (int chunk = 0; chunk < 5; chunk++) {
        const int base = chunk * 8;
        if (base >= nrows) break;
        __syncthreads();
        STOREX();
        __syncthreads();
        if (base + 8 < nrows) LOADX(base + 8, 64);
        #pragma unroll
        for (int rl = 0; rl < 4; rl++) {
            int ric = rh + 2 * rl;
            int rr  = base + ric;
            if (rr >= nrows) break;
            int R   = r0lo + rr;
            int krA = R - r0A, krB = R - r0B;
            bool vA = (unsigned)krA <= 30u, vB = (unsigned)krB <= 30u;
            if ((vA || vB) && lane <= 30) {
                const float4* kp = (const float4*)(s_stg + (ric * 32 + ccb1 + lane) * 20);
                float4 k0 = kp[0], k1 = kp[1], k2 = kp[2], k3 = kp[3];
                float a0 = qa[0].x*k0.x + qa[0].y*k0.y + qa[0].z*k0.z + qa[0].w*k0.w
                         + qa[1].x*k1.x + qa[1].y*k1.y + qa[1].z*k1.z + qa[1].w*k1.w
                         + qa[2].x*k2.x + qa[2].y*k2.y + qa[2].z*k2.z + qa[2].w*k2.w
                         + qa[3].x*k3.x + qa[3].y*k3.y + qa[3].z*k3.z + qa[3].w*k3.w;
                float a1 = qb[0].x*k0.x + qb[0].y*k0.y + qb[0].z*k0.z + qb[0].w*k0.w
                         + qb[1].x*k1.x + qb[1].y*k1.y + qb[1].z*k1.z + qb[1].w*k1.w
                         + qb[2].x*k2.x + qb[2].y*k2.y + qb[2].z*k2.z + qb[2].w*k2.w
                         + qb[3].x*k3.x + qb[3].y*k3.y + qb[3].z*k3.z + qb[3].w*k3.w;
                int crel  = crb1 + lane;
                int rrel0 = R - qi0 + 30;
                if (vA)
                    s_log[plA + krA * 32 + lane] =
                        __expf(a0 * 0.25f + __ldg(&rpb_h[(rrel0 - qrA) * 61 + crel]));
                if (vB)
                    s_log[plB + krB * 32 + lane] =
                        __expf(a1 * 0.25f + __ldg(&rpb_h[(rrel0 - qrB) * 61 + crel]));
            }
        }
    }

    LOADX(0, 128);              // prefetch V chunk 0 under softmax-sum
    __syncthreads();            // pass-1 writes visible

    // ---------------- pass 2: row sums (warp w <-> plane w) ----------------
    {
        float* p = s_log + w * 992;
        float s = 0.f;
        for (int n = lane; n < 992; n += 32) s += p[n];
        #pragma unroll
        for (int off = 16; off; off >>= 1)
            s += __shfl_xor_sync(0xffffffffu, s, off);
        if (lane == 0) s_rsum[w] = 1.0f / s;
    }

    // ---------------- pass 3: out = P.V, 4 queries per thread ----------------
    const int qc3 = w & 1;
    const int rq  = w >> 1;           // 0..3 row stripe
    const int ks  = lane >> 2;
    const int g   = lane & 3;
    const int ccb3 = c0c[qc3] - c0lo;
    float4 acc0 = make_float4(0.f,0.f,0.f,0.f);
    float4 acc1 = make_float4(0.f,0.f,0.f,0.f);
    float4 acc2 = make_float4(0.f,0.f,0.f,0.f);
    float4 acc3 = make_float4(0.f,0.f,0.f,0.f);

    for (int chunk = 0; chunk < 5; chunk++) {
        const int base = chunk * 8;
        if (base >= nrows) break;
        if (chunk) __syncthreads();
        STOREX();
        __syncthreads();
        if (base + 8 < nrows) LOADX(base + 8, 128);
        #pragma unroll
        for (int rl = 0; rl < 2; rl++) {
            int ric = rq + 4 * rl;
            int rr  = base + ric;
            if (rr >= nrows) break;
            int R = r0lo + rr;
            const float* vb = s_stg + (ric * 32 + ccb3 + ks * 4) * 20 + g * 4;
            float4 v0 = *(const float4*)(vb);
            float4 v1 = *(const float4*)(vb + 20);
            float4 v2 = *(const float4*)(vb + 40);
            float4 v3 = *(const float4*)(vb + 60);
            #pragma unroll
            for (int qr = 0; qr < 4; qr++) {
                int kr = R - r0r[qr];
                if ((unsigned)kr <= 30u) {
                    float4 l4 = *(const float4*)(s_log + (qc3 * 4 + qr) * 992 + kr * 32 + ks * 4);
                    float4* ac = (qr == 0) ? &acc0 : (qr == 1) ? &acc1 : (qr == 2) ? &acc2 : &acc3;
                    ac->x += l4.x*v0.x + l4.y*v1.x + l4.z*v2.x + l4.w*v3.x;
                    ac->y += l4.x*v0.y + l4.y*v1.y + l4.z*v2.y + l4.w*v3.y;
                    ac->z += l4.x*v0.z + l4.y*v1.z + l4.z*v2.z + l4.w*v3.z;
                    ac->w += l4.x*v0.w + l4.y*v1.w + l4.z*v2.w + l4.w*v3.w;
                }
            }
        }
    }
    // reduce over ks (lane bits 2..4)
    #pragma unroll
    for (int off = 4; off <= 16; off <<= 1) {
        acc0.x += __shfl_xor_sync(0xffffffffu, acc0.x, off);
        acc0.y += __shfl_xor_sync(0xffffffffu, acc0.y, off);
        acc0.z += __shfl_xor_sync(0xffffffffu, acc0.z, off);
        acc0.w += __shfl_xor_sync(0xffffffffu, acc0.w, off);
        acc1.x += __shfl_xor_sync(0xffffffffu, acc1.x, off);
        acc1.y += __shfl_xor_sync(0xffffffffu, acc1.y, off);
        acc1.z += __shfl_xor_sync(0xffffffffu, acc1.z, off);
        acc1.w += __shfl_xor_sync(0xffffffffu, acc1.w, off);
        acc2.x += __shfl_xor_sync(0xffffffffu, acc2.x, off);
        acc2.y += __shfl_xor_sync(0xffffffffu, acc2.y, off);
        acc2.z += __shfl_xor_sync(0xffffffffu, acc2.z, off);
        acc2.w += __shfl_xor_sync(0xffffffffu, acc2.w, off);
        acc3.x += __shfl_xor_sync(0xffffffffu, acc3.x, off);
        acc3.y += __shfl_xor_sync(0xffffffffu, acc3.y, off);
        acc3.z += __shfl_xor_sync(0xffffffffu, acc3.z, off);
        acc3.w += __shfl_xor_sync(0xffffffffu, acc3.w, off);
    }
    if (lane < 4) {          // ks==0 lanes: g = lane
        *(float4*)(s_part + (w * 4 + 0) * 16 + g * 4) = acc0;
        *(float4*)(s_part + (w * 4 + 1) * 16 + g * 4) = acc1;
        *(float4*)(s_part + (w * 4 + 2) * 16 + g * 4) = acc2;
        *(float4*)(s_part + (w * 4 + 3) * 16 + g * 4) = acc3;
    }
    __syncthreads();

    // combine partials (4 row-stripe warps per (qc,qr)) + scale; stage combo
    if (tid < 128) {
        int q = tid >> 4, ch = tid & 15;      // q = qc*4+qr
        int qc = q >> 2, qr = q & 3;
        float s = s_part[((0 * 2 + qc) * 4 + qr) * 16 + ch]
                + s_part[((1 * 2 + qc) * 4 + qr) * 16 + ch]
                + s_part[((2 * 2 + qc) * 4 + qr) * 16 + ch]
                + s_part[((3 * 2 + qc) * 4 + qr) * 16 + ch];
        s_out[q * 16 + ch] = s * s_rsum[q];
    }
    for (int e = tid; e < NOUT * 4; e += 256) {
        int o = e >> 2, cg = e & 3;
        float4 v = *(const float4*)(combo + o * 64 + h * 16 + cg * 4);
        float* d = s_stg + o * 17 + cg * 4;
        d[0] = v.x; d[1] = v.y; d[2] = v.z; d[3] = v.w;
    }
    __syncthreads();

    // epilogue: dst[pos,:] += out_slice @ combo_colslice
    {
        const int posg = (qi0 + (w & 3)) * WW + qj0 + (w >> 2);
        float sv[16];
        #pragma unroll
        for (int i = 0; i < 16; i++) sv[i] = s_out[w * 16 + i];
        #pragma unroll
        for (int tt = 0; tt < NOUT / 32; tt++) {
            int o = lane + 32 * tt;
            const float* cp = s_stg + o * 17;
            float a = 0.f;
            #pragma unroll
            for (int i = 0; i < 16; i++) a += sv[i] * cp[i];
            if (NOUT == 192 && h == 0) a += biasv[o];
            atomicAdd(dst + posg * NOUT + o, a);
        }
    }
}

// ---------------- conv init path: out = conv(x)@lin^T + bf ----------------
__device__ __forceinline__ void conv_body(
    const float* __restrict__ x, const float* __restrict__ linw,
    const float* __restrict__ dww, const float* __restrict__ bfv,
    float* __restrict__ out, int cb)
{
    extern __shared__ float sm[];
    float* B2  = sm;          // [64][68]
    float* As2 = sm + 4352;   // [16][68]
    float* sdw = sm + 5440;   // 576
    const int tid = threadIdx.x;
    const int m0 = cb * 16;

    #pragma unroll
    for (int l = 0; l < 16; l++) {
        int e = tid + l * 256;
        B2[(e >> 6) * 68 + (e & 63)] = linw[e];
    }
    #pragma unroll
    for (int l = 0; l < 3; l++) {
        int e = tid + l * 256;
        if (e < 576) sdw[e] = dww[e];
    }
    __syncthreads();
    #pragma unroll
    for (int l = 0; l < 4; l++) {
        int e = tid + l * 256;
        int r = e >> 6, c = e & 63;
        int p = m0 + r;
        int i = p / WW, j = p % WW;
        float a = 0.f;
        #pragma unroll
        for (int dy = 0; dy < 3; dy++) {
            int ii = i + dy - 1;
            if (ii < 0 || ii >= HH) continue;
            #pragma unroll
            for (int dx = 0; dx < 3; dx++) {
                int jj = j + dx - 1;
                if (jj < 0 || jj >= WW) continue;
                a += x[(ii * WW + jj) * 64 + c] * sdw[c * 9 + dy * 3 + dx];
            }
        }
        As2[r * 68 + c] = a;
    }
    __syncthreads();
    const int col = tid & 63;
    const int tg  = tid >> 6;
    float acc[4] = {0.f, 0.f, 0.f, 0.f};
    #pragma unroll
    for (int kb = 0; kb < 16; kb++) {
        float4 b2 = *(const float4*)&B2[col * 68 + kb * 4];
        #pragma unroll
        for (int i = 0; i < 4; i++) {
            float4 a2 = *(const float4*)&As2[(tg + 4 * i) * 68 + kb * 4];
            acc[i] += a2.x*b2.x + a2.y*b2.y + a2.z*b2.z + a2.w*b2.w;
        }
    }
    float bvv = bfv[col];
    #pragma unroll
    for (int i = 0; i < 4; i++)
        out[(m0 + tg + 4 * i) * 64 + col] = acc[i] + bvv;
}

__global__ __launch_bounds__(256) void layer1_kernel(
    const float* __restrict__ qkv, const float* __restrict__ rpb,
    const float* __restrict__ c1, const float* __restrict__ b1,
    float* __restrict__ qkv2,
    const float* __restrict__ x, const float* __restrict__ linw,
    const float* __restrict__ dww, const float* __restrict__ bfv,
    float* __restrict__ out)
{
    if (blockIdx.x < 648)
        attn_body<192>(qkv, rpb, c1, b1, qkv2, blockIdx.x);
    else
        conv_body(x, linw, dww, bfv, out, blockIdx.x - 648);
}

__global__ __launch_bounds__(256) void layer2_kernel(
    const float* __restrict__ qkv, const float* __restrict__ rpb,
    const float* __restrict__ c2, float* __restrict__ out)
{
    attn_body<64>(qkv, rpb, c2, (const float*)0, out, blockIdx.x);
}

// ---------------- launcher ----------------
extern "C" void kernel_launch(void* const* d_in, const int* in_sizes, int n_in,
                              void* d_out, int out_size)
{
    const float* x      = (const float*)d_in[0];
    const float* qkv_w1 = (const float*)d_in[3];
    const float* qkv_b1 = (const float*)d_in[4];
    const float* rpb1   = (const float*)d_in[5];
    const float* proj_w1= (const float*)d_in[6];
    const float* proj_b1= (const float*)d_in[7];
    const float* qkv_w2 = (const float*)d_in[8];
    const float* qkv_b2 = (const float*)d_in[9];
    const float* rpb2   = (const float*)d_in[10];
    const float* proj_w2= (const float*)d_in[11];
    const float* proj_b2= (const float*)d_in[12];
    const float* dw_w   = (const float*)d_in[13];
    const float* dw_b   = (const float*)d_in[14];
    const float* lin_w  = (const float*)d_in[15];
    const float* lin_b  = (const float*)d_in[16];
    float* out = (float*)d_out;

    float *p_qkv, *p_qkv2, *p_c1, *p_b1, *p_c2, *p_bf;
    cudaGetSymbolAddress((void**)&p_qkv,  g_qkv);
    cudaGetSymbolAddress((void**)&p_qkv2, g_qkv2);
    cudaGetSymbolAddress((void**)&p_c1,   g_c1);
    cudaGetSymbolAddress((void**)&p_b1,   g_b1);
    cudaGetSymbolAddress((void**)&p_c2,   g_c2);
    cudaGetSymbolAddress((void**)&p_bf,   g_bf);

    cudaFuncSetAttribute(layer1_kernel,
                         cudaFuncAttributeMaxDynamicSharedMemorySize, SMEM_BYTES);
    cudaFuncSetAttribute(layer2_kernel,
                         cudaFuncAttributeMaxDynamicSharedMemorySize, SMEM_BYTES);

    setup_kernel<<<343, 256, 5440 * 4>>>(
        x, qkv_w1, qkv_b1, qkv_w2, proj_w1, proj_b1, qkv_b2,
        lin_w, proj_w2, proj_b2, dw_b, lin_b,
        p_qkv, p_qkv2, p_c1, p_b1, p_c2, p_bf);
    layer1_kernel<<<729, 256, SMEM_BYTES>>>(
        p_qkv, rpb1, p_c1, p_b1, p_qkv2, x, lin_w, dw_w, p_bf, out);
    layer2_kernel<<<648, 256, SMEM_BYTES>>>(p_qkv2, rpb2, p_c2, out);
}